// round 13
// baseline (speedup 1.0000x reference)
#include <cuda_runtime.h>
#include <cuda_fp16.h>
#include <cstdint>

#define B_ 8
#define D_ 128
#define T_ 4096
#define Q_ 30
#define C_ 1024
#define BT_ (B_ * T_)
#define NOUT (B_ * D_ * T_)

#define TM 128
#define TN 128
#define NCHUNK 8
#define THREADS 512
#define DELTA 2.0f
#define CAP 32

// smem layout (bytes)
#define OFF_AS 0
#define SZ_AS (128 * 128 * 4)        // 65536  residual fp32, [k][row]
#define OFF_A16 (OFF_AS + SZ_AS)     // 65536
#define A16_PLANE 34816              // 128 rows x 272B fp16
#define OFF_BB (OFF_A16 + A16_PLANE) // 100352
#define BB_BUF 34816                 // 128 codes x 272B
#define SZ_BB (2 * BB_BUF)           // 69632 double buffered
#define OFF_C2 (OFF_BB + SZ_BB)      // 169984
#define SZ_C2 (C_ * 4)               // 4096
#define OFF_BI (OFF_C2 + SZ_C2)      // 174080
#define SZ_BI (TM * 4)               // 512
#define OFF_LR (OFF_BI + SZ_BI)      // 174592 (16 doubles)
#define OFF_CT (OFF_LR + 128)        // 174720 per-row candidate counts
#define OFF_CD (OFF_CT + 512)        // 175232 candidate codes (128 x CAP u16)
#define SMEM_BYTES (OFF_CD + 128 * CAP * 2)  // 183424

#define ROWSTRIDE 272

__device__ float g_c2[Q_ * C_];
__device__ double g_loss;
// fp16 high-plane codebook: [q][code][k]
__device__ __align__(16) __half g_bk[(size_t)Q_ * C_ * D_];

__device__ __forceinline__ void cp16(uint32_t saddr, const void* g) {
    asm volatile("cp.async.cg.shared.global [%0], [%1], 16;\n" ::"r"(saddr), "l"(g));
}
#define CP_COMMIT asm volatile("cp.async.commit_group;\n" ::: "memory")
#define CP_WAIT0 asm volatile("cp.async.wait_group 0;\n" ::: "memory")

__device__ __forceinline__ void ldm4(uint32_t& r0, uint32_t& r1, uint32_t& r2,
                                     uint32_t& r3, uint32_t addr) {
    asm volatile("ldmatrix.sync.aligned.m8n8.x4.shared.b16 {%0,%1,%2,%3}, [%4];"
                 : "=r"(r0), "=r"(r1), "=r"(r2), "=r"(r3)
                 : "r"(addr));
}

// fp16-accumulate MMA: D/C fragments are 2 regs of packed half2
__device__ __forceinline__ void mma16816h(uint32_t& d0, uint32_t& d1,
                                          uint32_t a0, uint32_t a1, uint32_t a2,
                                          uint32_t a3, uint32_t b0, uint32_t b1) {
    asm volatile(
        "mma.sync.aligned.m16n8k16.row.col.f16.f16.f16.f16 "
        "{%0,%1}, {%2,%3,%4,%5}, {%6,%7}, {%0,%1};"
        : "+r"(d0), "+r"(d1)
        : "r"(a0), "r"(a1), "r"(a2), "r"(a3), "r"(b0), "r"(b1));
}

// ---- prep: fp16 high plane of codebook ----
__global__ void k_prep(const float* __restrict__ cb) {
    int qc = blockIdx.x;
    int k = threadIdx.x;
    g_bk[(size_t)qc * D_ + k] = __float2half_rn(cb[(size_t)qc * D_ + k]);
}

// per-code squared norms + zero loss accumulator
__global__ void k_c2(const float* __restrict__ cb) {
    int code = blockIdx.x * 8 + (threadIdx.x >> 5);
    int lane = threadIdx.x & 31;
    float4 v = *(const float4*)(cb + (size_t)code * D_ + lane * 4);
    float s = v.x * v.x + v.y * v.y + v.z * v.z + v.w * v.w;
#pragma unroll
    for (int o = 16; o; o >>= 1) s += __shfl_down_sync(0xffffffffu, s, o);
    if (lane == 0) g_c2[code] = s;
    if (blockIdx.x == 0 && threadIdx.x == 0) g_loss = 0.0;
}

// ---- fused VQ: fp16 mma.sync screening (f16 accum) + exact fp32 rescore ----
__global__ __launch_bounds__(THREADS, 1) void k_vq(const float* __restrict__ x,
                                                   const float* __restrict__ cb_all,
                                                   float* __restrict__ out) {
    extern __shared__ char smem[];
    float* As = (float*)(smem + OFF_AS);
    float* c2s = (float*)(smem + OFF_C2);
    int* bidx = (int*)(smem + OFF_BI);
    double* lred = (double*)(smem + OFF_LR);
    int* ccnt = (int*)(smem + OFF_CT);
    unsigned short* cand = (unsigned short*)(smem + OFF_CD);

    const int tid = threadIdx.x;
    const int lane = tid & 31;
    const int w = tid >> 5;        // 0..15
    const int wr = w & 7;          // row-warp 0..7
    const int whalf = w >> 3;      // code half 0/1
    const int bt0 = blockIdx.x * TM;
    const int b = bt0 / T_;
    const int t0 = bt0 % T_;
    const float* xb = x + (size_t)b * D_ * T_ + t0;

    const uint32_t sBase = (uint32_t)__cvta_generic_to_shared(smem);
    const uint32_t sA16 = sBase + OFF_A16;
    const uint32_t sBB = sBase + OFF_BB;

    const int arow = 16 * wr + (lane & 15);
    const uint32_t aoff = (uint32_t)(arow * ROWSTRIDE + ((lane >= 16) ? 16 : 0));
    const int brow = (lane & 7) + ((lane >= 16) ? 8 : 0);
    const uint32_t boff =
        (uint32_t)(whalf * 64 * ROWSTRIDE + brow * ROWSTRIDE + ((lane & 8) ? 16 : 0));

    // rows owned by this warp's D fragments
    const int R0 = 16 * wr + (lane >> 2);
    const int R1 = R0 + 8;

    // fused-update mapping: 512 thr = (row, quarter)
    const int urow = tid & 127;
    const int uq = tid >> 7;       // 0..3 -> 32 d's each
    const int udbase = uq * 32;

    // load residual tile As[k*128+row]
    for (int i = 0; i < 32; ++i) {
        int idx = i * THREADS + tid;
        int d = idx >> 7, tc = idx & 127;
        As[d * 128 + tc] = xb[(size_t)d * T_ + tc];
    }
    __syncthreads();

    // initial fp16 convert (A16 plane for q=0)
    {
        uint32_t* dst = (uint32_t*)(smem + OFF_A16 + urow * ROWSTRIDE);
#pragma unroll 8
        for (int k = udbase; k < udbase + 32; k += 2) {
            float a0 = As[k * 128 + urow];
            float a1 = As[(k + 1) * 128 + urow];
            dst[k >> 1] = (uint32_t)__half_as_ushort(__float2half_rn(a0)) |
                          ((uint32_t)__half_as_ushort(__float2half_rn(a1)) << 16);
        }
    }
    if (tid < TM) ccnt[tid] = 0;

    // prefetch q=0 chunk 0 (cross-q prefetch handles the rest)
    {
#pragma unroll
        for (int it = 0; it < 4; ++it) {
            int u = it * THREADS + tid;
            int code = u >> 4, blk = u & 15;
            cp16(sBB + code * ROWSTRIDE + blk * 16,
                 g_bk + (size_t)code * D_ + blk * 8);
        }
        CP_COMMIT;
    }

    double dloss = 0.0;

    for (int q = 0; q < Q_; ++q) {
        const float* cbq = cb_all + (size_t)q * C_ * D_;
        for (int i = tid; i < C_; i += THREADS) c2s[i] = g_c2[q * C_ + i];
        __syncthreads();  // A16 (from prev fused update / initial), c2s, ccnt ready

        const float INF = __int_as_float(0x7f800000);
        float rm0 = INF, rm1 = INF;

        for (int ch = 0; ch < NCHUNK; ++ch) {
            CP_WAIT0;
            __syncthreads();

            // prefetch: next chunk of this q, or chunk 0 of q+1 (into buf0,
            // whose last reader was chunk NCHUNK-2 — safe after the sync above)
            if (ch + 1 < NCHUNK || q + 1 < Q_) {
                const __half* srcn = (ch + 1 < NCHUNK)
                    ? g_bk + ((size_t)q * C_ + (ch + 1) * TN) * D_
                    : g_bk + ((size_t)(q + 1)) * C_ * D_;
                uint32_t dstb = sBB + ((ch + 1) & 1) * BB_BUF;
#pragma unroll
                for (int it = 0; it < 4; ++it) {
                    int u = it * THREADS + tid;
                    int code = u >> 4, blk = u & 15;
                    cp16(dstb + code * ROWSTRIDE + blk * 16,
                         srcn + (size_t)code * D_ + blk * 8);
                }
                CP_COMMIT;
            }

            const uint32_t bufB = sBB + (ch & 1) * BB_BUF;

            uint32_t cd[8][2];
#pragma unroll
            for (int nt = 0; nt < 8; ++nt) { cd[nt][0] = 0u; cd[nt][1] = 0u; }

#pragma unroll
            for (int kk = 0; kk < 8; ++kk) {
                uint32_t a0[4];
                ldm4(a0[0], a0[1], a0[2], a0[3], sA16 + aoff + kk * 32);
#pragma unroll
                for (int ntp = 0; ntp < 4; ++ntp) {
                    uint32_t b0[4];
                    uint32_t bbase = bufB + boff + ntp * 16 * ROWSTRIDE + kk * 32;
                    ldm4(b0[0], b0[1], b0[2], b0[3], bbase);
                    mma16816h(cd[2 * ntp][0], cd[2 * ntp][1],
                              a0[0], a0[1], a0[2], a0[3], b0[0], b0[1]);
                    mma16816h(cd[2 * ntp + 1][0], cd[2 * ntp + 1][1],
                              a0[0], a0[1], a0[2], a0[3], b0[2], b0[3]);
                }
            }

            // fast scores for this warp's code half
            float sc[8][4];
            float cm0 = INF, cm1 = INF;
            const int cgb = ch * TN + whalf * 64 + 2 * (lane & 3);
#pragma unroll
            for (int nt = 0; nt < 8; ++nt) {
                int cg = cgb + nt * 8;
                float c2a = c2s[cg], c2b = c2s[cg + 1];
                float2 vlo = __half22float2(*reinterpret_cast<__half2*>(&cd[nt][0]));
                float2 vhi = __half22float2(*reinterpret_cast<__half2*>(&cd[nt][1]));
                float s0 = fmaf(-2.f, vlo.x, c2a);
                float s1 = fmaf(-2.f, vlo.y, c2b);
                float s2 = fmaf(-2.f, vhi.x, c2a);
                float s3 = fmaf(-2.f, vhi.y, c2b);
                sc[nt][0] = s0; sc[nt][1] = s1; sc[nt][2] = s2; sc[nt][3] = s3;
                cm0 = fminf(cm0, fminf(s0, s1));
                cm1 = fminf(cm1, fminf(s2, s3));
            }
#pragma unroll
            for (int m = 1; m <= 2; m <<= 1) {
                cm0 = fminf(cm0, __shfl_xor_sync(0xffffffffu, cm0, m));
                cm1 = fminf(cm1, __shfl_xor_sync(0xffffffffu, cm1, m));
            }
            rm0 = fminf(rm0, cm0);
            rm1 = fminf(rm1, cm1);
            float th0 = rm0 + DELTA, th1 = rm1 + DELTA;

            // append candidates (guarded: most chunks contribute none)
            if (cm0 < th0) {
#pragma unroll
                for (int nt = 0; nt < 8; ++nt) {
                    int cg = cgb + nt * 8;
                    if (sc[nt][0] < th0) { int p = atomicAdd(&ccnt[R0], 1); if (p < CAP) cand[R0 * CAP + p] = (unsigned short)cg; }
                    if (sc[nt][1] < th0) { int p = atomicAdd(&ccnt[R0], 1); if (p < CAP) cand[R0 * CAP + p] = (unsigned short)(cg + 1); }
                }
            }
            if (cm1 < th1) {
#pragma unroll
                for (int nt = 0; nt < 8; ++nt) {
                    int cg = cgb + nt * 8;
                    if (sc[nt][2] < th1) { int p = atomicAdd(&ccnt[R1], 1); if (p < CAP) cand[R1 * CAP + p] = (unsigned short)cg; }
                    if (sc[nt][3] < th1) { int p = atomicAdd(&ccnt[R1], 1); if (p < CAP) cand[R1 * CAP + p] = (unsigned short)(cg + 1); }
                }
            }
        }
        __syncthreads();  // candidates visible

        // ---- exact fp32 rescore, split across warp halves:
        //      whalf==0 -> R0 rows, whalf==1 -> R1 rows (each row exactly once)
        {
            int r = whalf ? R1 : R0;
            int n = ccnt[r];
            bool ovf = n > CAP;
            if (ovf) n = C_;  // guaranteed-correct fallback
            const float INF2 = __int_as_float(0x7f800000);
            float bv = INF2;
            int bi = 0x7fffffff;
            for (int i = lane & 3; i < n; i += 4) {
                int code = ovf ? i : (int)cand[r * CAP + i];
                const float4* cp4 = (const float4*)(cbq + (size_t)code * D_);
                float s = 0.f;
#pragma unroll 8
                for (int dq = 0; dq < 32; ++dq) {
                    float4 cv = cp4[dq];
                    s = fmaf(As[(4 * dq + 0) * 128 + r], cv.x, s);
                    s = fmaf(As[(4 * dq + 1) * 128 + r], cv.y, s);
                    s = fmaf(As[(4 * dq + 2) * 128 + r], cv.z, s);
                    s = fmaf(As[(4 * dq + 3) * 128 + r], cv.w, s);
                }
                float scv = fmaf(-2.f, s, c2s[code]);
                if (scv < bv || (scv == bv && code < bi)) { bv = scv; bi = code; }
            }
#pragma unroll
            for (int m = 1; m <= 2; m <<= 1) {
                float ov = __shfl_xor_sync(0xffffffffu, bv, m);
                int oi = __shfl_xor_sync(0xffffffffu, bi, m);
                if (ov < bv || (ov == bv && oi < bi)) { bv = ov; bi = oi; }
            }
            if ((lane & 3) == 0) bidx[r] = bi;
        }
        __syncthreads();  // bidx ready; screening reads of A16 done

        // ---- fused: residual update + loss + fp16 convert for next q ----
        {
            const float4* cp4 =
                (const float4*)(cbq + (size_t)bidx[urow] * D_ + udbase);
            uint32_t* dst = (uint32_t*)(smem + OFF_A16 + urow * ROWSTRIDE);
            float ls = 0.f;
#pragma unroll
            for (int i = 0; i < 8; ++i) {
                float4 cv = cp4[i];
                int d = udbase + 4 * i;
                float n0 = As[(d + 0) * 128 + urow] - cv.x;
                float n1 = As[(d + 1) * 128 + urow] - cv.y;
                float n2 = As[(d + 2) * 128 + urow] - cv.z;
                float n3 = As[(d + 3) * 128 + urow] - cv.w;
                As[(d + 0) * 128 + urow] = n0;
                As[(d + 1) * 128 + urow] = n1;
                As[(d + 2) * 128 + urow] = n2;
                As[(d + 3) * 128 + urow] = n3;
                ls += n0 * n0 + n1 * n1 + n2 * n2 + n3 * n3;
                if (q + 1 < Q_) {
                    dst[(d >> 1) + 0] = (uint32_t)__half_as_ushort(__float2half_rn(n0)) |
                                        ((uint32_t)__half_as_ushort(__float2half_rn(n1)) << 16);
                    dst[(d >> 1) + 1] = (uint32_t)__half_as_ushort(__float2half_rn(n2)) |
                                        ((uint32_t)__half_as_ushort(__float2half_rn(n3)) << 16);
                }
            }
            dloss += (double)ls;
        }
        if (tid < TM) ccnt[tid] = 0;  // after rescore read, before next q
        // next q's top-of-loop __syncthreads() orders A16/As/ccnt for screening
    }

    __syncthreads();
    // quantized = x - residual_final, straight [B,D,T]
    for (int i = 0; i < 32; ++i) {
        int idx = i * THREADS + tid;
        int d = idx >> 7, tc = idx & 127;
        size_t gi = (size_t)d * T_ + tc;
        out[(size_t)b * D_ * T_ + t0 + gi] = xb[gi] - As[d * 128 + tc];
    }

    // loss reduce
    double v = dloss;
#pragma unroll
    for (int o = 16; o; o >>= 1) v += __shfl_down_sync(0xffffffffu, v, o);
    if (lane == 0) lred[w] = v;
    __syncthreads();
    if (tid == 0) {
        double tot = 0.0;
#pragma unroll
        for (int i = 0; i < 16; ++i) tot += lred[i];
        atomicAdd(&g_loss, tot);
    }
}

__global__ void k_loss(float* __restrict__ out, int out_size) {
    if (out_size > NOUT) out[NOUT] = (float)(g_loss / (double)((size_t)BT_ * D_));
}

extern "C" void kernel_launch(void* const* d_in, const int* in_sizes, int n_in,
                              void* d_out, int out_size) {
    const float* x = (const float*)d_in[0];
    const float* cb = (const float*)d_in[1];
    float* out = (float*)d_out;

    cudaFuncSetAttribute(k_vq, cudaFuncAttributeMaxDynamicSharedMemorySize, SMEM_BYTES);

    k_prep<<<Q_ * C_, 128>>>(cb);
    k_c2<<<(Q_ * C_) / 8, 256>>>(cb);
    k_vq<<<BT_ / TM, THREADS, SMEM_BYTES>>>(x, cb, out);
    k_loss<<<1, 1>>>(out, out_size);
}

// round 14
// speedup vs baseline: 1.0494x; 1.0494x over previous
#include <cuda_runtime.h>
#include <cuda_fp16.h>
#include <cstdint>

#define B_ 8
#define D_ 128
#define T_ 4096
#define Q_ 30
#define C_ 1024
#define BT_ (B_ * T_)
#define NOUT (B_ * D_ * T_)

#define TM 128
#define TN 128
#define NCHUNK 8
#define THREADS 512
#define DELTA 0.75f
#define CAP 32

// smem layout (bytes)
#define OFF_AS 0
#define SZ_AS (128 * 128 * 4)        // 65536  residual fp32, [k][row]
#define OFF_A16 (OFF_AS + SZ_AS)     // 65536
#define A16_PLANE 34816              // 128 rows x 272B fp16
#define OFF_BB (OFF_A16 + A16_PLANE) // 100352
#define BB_BUF 34816                 // 128 codes x 272B
#define SZ_BB (2 * BB_BUF)           // 69632 double buffered
#define OFF_C2 (OFF_BB + SZ_BB)      // 169984
#define SZ_C2 (C_ * 4)               // 4096
#define OFF_BI (OFF_C2 + SZ_C2)      // 174080
#define SZ_BI (TM * 4)               // 512
#define OFF_LR (OFF_BI + SZ_BI)      // 174592 (16 doubles)
#define OFF_CT (OFF_LR + 128)        // 174720 per-row candidate counts
#define OFF_CD (OFF_CT + 512)        // 175232 candidate codes (128 x CAP u16)
#define SMEM_BYTES (OFF_CD + 128 * CAP * 2)  // 183424

#define ROWSTRIDE 272

__device__ float g_c2[Q_ * C_];
__device__ double g_loss;
// fp16 high-plane codebook: [q][code][k]
__device__ __align__(16) __half g_bk[(size_t)Q_ * C_ * D_];

__device__ __forceinline__ void cp16(uint32_t saddr, const void* g) {
    asm volatile("cp.async.cg.shared.global [%0], [%1], 16;\n" ::"r"(saddr), "l"(g));
}
#define CP_COMMIT asm volatile("cp.async.commit_group;\n" ::: "memory")
#define CP_WAIT0 asm volatile("cp.async.wait_group 0;\n" ::: "memory")

__device__ __forceinline__ void ldm4(uint32_t& r0, uint32_t& r1, uint32_t& r2,
                                     uint32_t& r3, uint32_t addr) {
    asm volatile("ldmatrix.sync.aligned.m8n8.x4.shared.b16 {%0,%1,%2,%3}, [%4];"
                 : "=r"(r0), "=r"(r1), "=r"(r2), "=r"(r3)
                 : "r"(addr));
}

__device__ __forceinline__ void mma16816(float& c0, float& c1, float& c2, float& c3,
                                         uint32_t a0, uint32_t a1, uint32_t a2,
                                         uint32_t a3, uint32_t b0, uint32_t b1) {
    asm volatile(
        "mma.sync.aligned.m16n8k16.row.col.f32.f16.f16.f32 "
        "{%0,%1,%2,%3}, {%4,%5,%6,%7}, {%8,%9}, {%0,%1,%2,%3};"
        : "+f"(c0), "+f"(c1), "+f"(c2), "+f"(c3)
        : "r"(a0), "r"(a1), "r"(a2), "r"(a3), "r"(b0), "r"(b1));
}

// ---- prep: fp16 high plane of codebook ----
__global__ void k_prep(const float* __restrict__ cb) {
    int qc = blockIdx.x;
    int k = threadIdx.x;
    g_bk[(size_t)qc * D_ + k] = __float2half_rn(cb[(size_t)qc * D_ + k]);
}

// per-code squared norms + zero loss accumulator
__global__ void k_c2(const float* __restrict__ cb) {
    int code = blockIdx.x * 8 + (threadIdx.x >> 5);
    int lane = threadIdx.x & 31;
    float4 v = *(const float4*)(cb + (size_t)code * D_ + lane * 4);
    float s = v.x * v.x + v.y * v.y + v.z * v.z + v.w * v.w;
#pragma unroll
    for (int o = 16; o; o >>= 1) s += __shfl_down_sync(0xffffffffu, s, o);
    if (lane == 0) g_c2[code] = s;
    if (blockIdx.x == 0 && threadIdx.x == 0) g_loss = 0.0;
}

// ---- fused VQ: fp16 mma.sync screening + exact fp32 candidate rescore ----
__global__ __launch_bounds__(THREADS, 1) void k_vq(const float* __restrict__ x,
                                                   const float* __restrict__ cb_all,
                                                   float* __restrict__ out) {
    extern __shared__ char smem[];
    float* As = (float*)(smem + OFF_AS);
    float* c2s = (float*)(smem + OFF_C2);
    int* bidx = (int*)(smem + OFF_BI);
    double* lred = (double*)(smem + OFF_LR);
    int* ccnt = (int*)(smem + OFF_CT);
    unsigned short* cand = (unsigned short*)(smem + OFF_CD);

    const int tid = threadIdx.x;
    const int lane = tid & 31;
    const int w = tid >> 5;        // 0..15
    const int wr = w & 7;          // row-warp 0..7
    const int whalf = w >> 3;      // code half 0/1
    const int bt0 = blockIdx.x * TM;
    const int b = bt0 / T_;
    const int t0 = bt0 % T_;
    const float* xb = x + (size_t)b * D_ * T_ + t0;

    const uint32_t sBase = (uint32_t)__cvta_generic_to_shared(smem);
    const uint32_t sA16 = sBase + OFF_A16;
    const uint32_t sBB = sBase + OFF_BB;

    const int arow = 16 * wr + (lane & 15);
    const uint32_t aoff = (uint32_t)(arow * ROWSTRIDE + ((lane >= 16) ? 16 : 0));
    const int brow = (lane & 7) + ((lane >= 16) ? 8 : 0);
    const uint32_t boff =
        (uint32_t)(whalf * 64 * ROWSTRIDE + brow * ROWSTRIDE + ((lane & 8) ? 16 : 0));

    // rows owned by this warp's D fragments
    const int R0 = 16 * wr + (lane >> 2);
    const int R1 = R0 + 8;

    // fused-update mapping: 512 thr = (row, quarter)
    const int urow = tid & 127;
    const int uq = tid >> 7;       // 0..3 -> 32 d's each
    const int udbase = uq * 32;

    // load residual tile As[k*128+row]
    for (int i = 0; i < 32; ++i) {
        int idx = i * THREADS + tid;
        int d = idx >> 7, tc = idx & 127;
        As[d * 128 + tc] = xb[(size_t)d * T_ + tc];
    }
    __syncthreads();

    // initial fp16 convert (A16 plane for q=0), 64-bit stores
    {
        uint2* dst = (uint2*)(smem + OFF_A16 + urow * ROWSTRIDE);
#pragma unroll 4
        for (int k = udbase; k < udbase + 32; k += 4) {
            float a0 = As[k * 128 + urow];
            float a1 = As[(k + 1) * 128 + urow];
            float a2 = As[(k + 2) * 128 + urow];
            float a3 = As[(k + 3) * 128 + urow];
            uint2 p;
            p.x = (uint32_t)__half_as_ushort(__float2half_rn(a0)) |
                  ((uint32_t)__half_as_ushort(__float2half_rn(a1)) << 16);
            p.y = (uint32_t)__half_as_ushort(__float2half_rn(a2)) |
                  ((uint32_t)__half_as_ushort(__float2half_rn(a3)) << 16);
            dst[k >> 2] = p;
        }
    }
    if (tid < TM) ccnt[tid] = 0;

    // prefetch q=0 chunk 0 (cross-q prefetch handles the rest)
    {
#pragma unroll
        for (int it = 0; it < 4; ++it) {
            int u = it * THREADS + tid;
            int code = u >> 4, blk = u & 15;
            cp16(sBB + code * ROWSTRIDE + blk * 16,
                 g_bk + (size_t)code * D_ + blk * 8);
        }
        CP_COMMIT;
    }

    double dloss = 0.0;

    for (int q = 0; q < Q_; ++q) {
        const float* cbq = cb_all + (size_t)q * C_ * D_;
        for (int i = tid; i < C_; i += THREADS) c2s[i] = g_c2[q * C_ + i];
        __syncthreads();  // A16 (from prev fused update / initial), c2s, ccnt ready

        // ---- hoist A fragments for the whole q (invariant across chunks) ----
        uint32_t afr[8][4];
#pragma unroll
        for (int kk = 0; kk < 8; ++kk)
            ldm4(afr[kk][0], afr[kk][1], afr[kk][2], afr[kk][3],
                 sA16 + aoff + kk * 32);

        const float INF = __int_as_float(0x7f800000);
        float rm0 = INF, rm1 = INF;

        for (int ch = 0; ch < NCHUNK; ++ch) {
            CP_WAIT0;
            __syncthreads();

            // prefetch: next chunk of this q, or chunk 0 of q+1 (into buf0,
            // whose last reader was chunk NCHUNK-2 — safe after the sync above)
            if (ch + 1 < NCHUNK || q + 1 < Q_) {
                const __half* srcn = (ch + 1 < NCHUNK)
                    ? g_bk + ((size_t)q * C_ + (ch + 1) * TN) * D_
                    : g_bk + ((size_t)(q + 1)) * C_ * D_;
                uint32_t dstb = sBB + ((ch + 1) & 1) * BB_BUF;
#pragma unroll
                for (int it = 0; it < 4; ++it) {
                    int u = it * THREADS + tid;
                    int code = u >> 4, blk = u & 15;
                    cp16(dstb + code * ROWSTRIDE + blk * 16,
                         srcn + (size_t)code * D_ + blk * 8);
                }
                CP_COMMIT;
            }

            const uint32_t bufB = sBB + (ch & 1) * BB_BUF;

            float c[8][4];
#pragma unroll
            for (int nt = 0; nt < 8; ++nt)
#pragma unroll
                for (int j = 0; j < 4; ++j) c[nt][j] = 0.f;

#pragma unroll
            for (int kk = 0; kk < 8; ++kk) {
#pragma unroll
                for (int ntp = 0; ntp < 4; ++ntp) {
                    uint32_t b0[4];
                    uint32_t bbase = bufB + boff + ntp * 16 * ROWSTRIDE + kk * 32;
                    ldm4(b0[0], b0[1], b0[2], b0[3], bbase);
                    float* cl = c[2 * ntp];
                    float* ch2 = c[2 * ntp + 1];
                    mma16816(cl[0], cl[1], cl[2], cl[3],
                             afr[kk][0], afr[kk][1], afr[kk][2], afr[kk][3],
                             b0[0], b0[1]);
                    mma16816(ch2[0], ch2[1], ch2[2], ch2[3],
                             afr[kk][0], afr[kk][1], afr[kk][2], afr[kk][3],
                             b0[2], b0[3]);
                }
            }

            // pass 1: chunk min directly from accumulators (no sc array)
            float cm0 = INF, cm1 = INF;
            const int cgb = ch * TN + whalf * 64 + 2 * (lane & 3);
#pragma unroll
            for (int nt = 0; nt < 8; ++nt) {
                int cg = cgb + nt * 8;
                float c2a = c2s[cg], c2b = c2s[cg + 1];
                cm0 = fminf(cm0, fminf(fmaf(-2.f, c[nt][0], c2a),
                                       fmaf(-2.f, c[nt][1], c2b)));
                cm1 = fminf(cm1, fminf(fmaf(-2.f, c[nt][2], c2a),
                                       fmaf(-2.f, c[nt][3], c2b)));
            }
#pragma unroll
            for (int m = 1; m <= 2; m <<= 1) {
                cm0 = fminf(cm0, __shfl_xor_sync(0xffffffffu, cm0, m));
                cm1 = fminf(cm1, __shfl_xor_sync(0xffffffffu, cm1, m));
            }
            rm0 = fminf(rm0, cm0);
            rm1 = fminf(rm1, cm1);
            float th0 = rm0 + DELTA, th1 = rm1 + DELTA;

            // pass 2: recompute scores and append, only if this chunk can contribute
            if (cm0 < th0) {
#pragma unroll
                for (int nt = 0; nt < 8; ++nt) {
                    int cg = cgb + nt * 8;
                    float s0 = fmaf(-2.f, c[nt][0], c2s[cg]);
                    float s1 = fmaf(-2.f, c[nt][1], c2s[cg + 1]);
                    if (s0 < th0) { int p = atomicAdd(&ccnt[R0], 1); if (p < CAP) cand[R0 * CAP + p] = (unsigned short)cg; }
                    if (s1 < th0) { int p = atomicAdd(&ccnt[R0], 1); if (p < CAP) cand[R0 * CAP + p] = (unsigned short)(cg + 1); }
                }
            }
            if (cm1 < th1) {
#pragma unroll
                for (int nt = 0; nt < 8; ++nt) {
                    int cg = cgb + nt * 8;
                    float s2 = fmaf(-2.f, c[nt][2], c2s[cg]);
                    float s3 = fmaf(-2.f, c[nt][3], c2s[cg + 1]);
                    if (s2 < th1) { int p = atomicAdd(&ccnt[R1], 1); if (p < CAP) cand[R1 * CAP + p] = (unsigned short)cg; }
                    if (s3 < th1) { int p = atomicAdd(&ccnt[R1], 1); if (p < CAP) cand[R1 * CAP + p] = (unsigned short)(cg + 1); }
                }
            }
        }
        __syncthreads();  // candidates visible

        // ---- exact fp32 rescore, split across warp halves:
        //      whalf==0 -> R0 rows, whalf==1 -> R1 rows (each row exactly once)
        {
            int r = whalf ? R1 : R0;
            int n = ccnt[r];
            bool ovf = n > CAP;
            if (ovf) n = C_;  // guaranteed-correct fallback
            const float INF2 = __int_as_float(0x7f800000);
            float bv = INF2;
            int bi = 0x7fffffff;
            for (int i = lane & 3; i < n; i += 4) {
                int code = ovf ? i : (int)cand[r * CAP + i];
                const float4* cp4 = (const float4*)(cbq + (size_t)code * D_);
                float s = 0.f;
#pragma unroll 8
                for (int dq = 0; dq < 32; ++dq) {
                    float4 cv = cp4[dq];
                    s = fmaf(As[(4 * dq + 0) * 128 + r], cv.x, s);
                    s = fmaf(As[(4 * dq + 1) * 128 + r], cv.y, s);
                    s = fmaf(As[(4 * dq + 2) * 128 + r], cv.z, s);
                    s = fmaf(As[(4 * dq + 3) * 128 + r], cv.w, s);
                }
                float scv = fmaf(-2.f, s, c2s[code]);
                if (scv < bv || (scv == bv && code < bi)) { bv = scv; bi = code; }
            }
#pragma unroll
            for (int m = 1; m <= 2; m <<= 1) {
                float ov = __shfl_xor_sync(0xffffffffu, bv, m);
                int oi = __shfl_xor_sync(0xffffffffu, bi, m);
                if (ov < bv || (ov == bv && oi < bi)) { bv = ov; bi = oi; }
            }
            if ((lane & 3) == 0) bidx[r] = bi;
        }
        __syncthreads();  // bidx ready; screening reads of A16 done

        // ---- fused: residual update + loss + fp16 convert for next q ----
        {
            const float4* cp4 =
                (const float4*)(cbq + (size_t)bidx[urow] * D_ + udbase);
            uint2* dst = (uint2*)(smem + OFF_A16 + urow * ROWSTRIDE);
            float ls = 0.f;
#pragma unroll
            for (int i = 0; i < 8; ++i) {
                float4 cv = cp4[i];
                int d = udbase + 4 * i;
                float n0 = As[(d + 0) * 128 + urow] - cv.x;
                float n1 = As[(d + 1) * 128 + urow] - cv.y;
                float n2 = As[(d + 2) * 128 + urow] - cv.z;
                float n3 = As[(d + 3) * 128 + urow] - cv.w;
                As[(d + 0) * 128 + urow] = n0;
                As[(d + 1) * 128 + urow] = n1;
                As[(d + 2) * 128 + urow] = n2;
                As[(d + 3) * 128 + urow] = n3;
                ls += n0 * n0 + n1 * n1 + n2 * n2 + n3 * n3;
                if (q + 1 < Q_) {
                    uint2 p;
                    p.x = (uint32_t)__half_as_ushort(__float2half_rn(n0)) |
                          ((uint32_t)__half_as_ushort(__float2half_rn(n1)) << 16);
                    p.y = (uint32_t)__half_as_ushort(__float2half_rn(n2)) |
                          ((uint32_t)__half_as_ushort(__float2half_rn(n3)) << 16);
                    dst[d >> 2] = p;
                }
            }
            dloss += (double)ls;
        }
        if (tid < TM) ccnt[tid] = 0;  // after rescore read, before next q
        // next q's top-of-loop __syncthreads() orders A16/As/ccnt for screening
    }

    __syncthreads();
    // quantized = x - residual_final, straight [B,D,T]
    for (int i = 0; i < 32; ++i) {
        int idx = i * THREADS + tid;
        int d = idx >> 7, tc = idx & 127;
        size_t gi = (size_t)d * T_ + tc;
        out[(size_t)b * D_ * T_ + t0 + gi] = xb[gi] - As[d * 128 + tc];
    }

    // loss reduce
    double v = dloss;
#pragma unroll
    for (int o = 16; o; o >>= 1) v += __shfl_down_sync(0xffffffffu, v, o);
    if (lane == 0) lred[w] = v;
    __syncthreads();
    if (tid == 0) {
        double tot = 0.0;
#pragma unroll
        for (int i = 0; i < 16; ++i) tot += lred[i];
        atomicAdd(&g_loss, tot);
    }
}

__global__ void k_loss(float* __restrict__ out, int out_size) {
    if (out_size > NOUT) out[NOUT] = (float)(g_loss / (double)((size_t)BT_ * D_));
}

extern "C" void kernel_launch(void* const* d_in, const int* in_sizes, int n_in,
                              void* d_out, int out_size) {
    const float* x = (const float*)d_in[0];
    const float* cb = (const float*)d_in[1];
    float* out = (float*)d_out;

    cudaFuncSetAttribute(k_vq, cudaFuncAttributeMaxDynamicSharedMemorySize, SMEM_BYTES);

    k_prep<<<Q_ * C_, 128>>>(cb);
    k_c2<<<(Q_ * C_) / 8, 256>>>(cb);
    k_vq<<<BT_ / TM, THREADS, SMEM_BYTES>>>(x, cb, out);
    k_loss<<<1, 1>>>(out, out_size);
}